// round 12
// baseline (speedup 1.0000x reference)
#include <cuda_runtime.h>
#include <math.h>

#define IMG_H 480
#define IMG_W 640
#define NB    4
#define PS    (IMG_H * IMG_W)

#define BTX   32
#define BTY   4
#define PXT   2                    // pixels per thread along x
#define TPW   (BTX * PXT)          // 64
#define TPH   BTY                  // 4
#define HALO  6
#define TILE_W (TPW + 2 * HALO)    // 76 floats
#define TILE_H (TPH + 2 * HALO)    // 16

// float bit patterns of -2.0f / 0.0f / +2.0f live entirely in bits [31:30]
#define FB(o)  ((o) == -2 ? 0xC0000000u : ((o) == 2 ? 0x40000000u : 0u))
// pack (off_h, off_w) for candidate k: oh bits in [31:30], ow bits in [29:28]
#define PKC(k) (FB(2*((k)/3 - 1)) | (FB(2*((k)%3 - 1)) >> 2))

__device__ __forceinline__ constexpr unsigned maskRC(int R, int C) {
    // col taps (j=1,7): k in {1,4,7}; row taps (j=3,5): k in {3,4,5}; else all 9
    return ((R != 1) && (C == 1)) ? 0x92u :
           ((R == 1) && (C != 1)) ? 0x38u : 0x1FFu;
}
__device__ __forceinline__ constexpr int firstK(unsigned m) {
    return (m & 1u) ? 0 : ((m & 2u) ? 1 : 3);
}

template<bool SAFE>
__device__ __forceinline__ void compute2(
    const float (&tile)[TILE_H][TILE_W],
    int tx, int ty, int x0, int y,
    float* __restrict__ b0, float* __restrict__ b1, float* __restrict__ b2)
{
    const float cen0 = tile[ty + HALO][2 * tx + HALO];
    const float cen1 = tile[ty + HALO][2 * tx + HALO + 1];

#pragma unroll
    for (int R = 0; R < 3; R++) {
        // this tap-row group needs grid rows 2R..2R+2 -> tile rows ty+4R+2r,
        // cols 2tx .. 2tx+13 (14 consecutive floats = 7 LDS.64 per row)
        float s[3][14];
#pragma unroll
        for (int r = 0; r < 3; r++) {
            const float2* src = (const float2*)&tile[ty + 4 * R + 2 * r][2 * tx];
#pragma unroll
            for (int q = 0; q < 7; q++) {
                float2 v = src[q];
                s[r][2 * q]     = v.x;
                s[r][2 * q + 1] = v.y;
            }
        }

        bool yok = true;
        if (!SAFE) yok = (unsigned)(y + 4 * (R - 1)) < (unsigned)IMG_H;

#pragma unroll
        for (int C = 0; C < 3; C++) {
            const int j = 3 * R + C;
            const unsigned mask = maskRC(R, C);
            const int fk = firstK(mask);

            unsigned pk0, pk1;
#pragma unroll
            for (int p = 0; p < PXT; p++) {
                const float cen = (p == 0) ? cen0 : cen1;
                float best = 0.0f;
                unsigned pk = 0u;
                bool first = true;
#pragma unroll
                for (int k = 0; k < 9; k++) {
                    if (!((mask >> k) & 1u)) continue;
                    const int r = k / 3;
                    const int c = k % 3;
                    float v = s[r][p + 4 * C + 2 * c] - cen;
                    if (first) { best = v; pk = PKC(k); first = false; }
                    else {
                        bool pr = fabsf(v) < fabsf(best);  // strict <: first wins
                        best = pr ? v : best;
                        pk   = pr ? PKC(k) : pk;
                    }
                }
                if (!SAFE) {
                    // intermediate index OOB -> all allowed samples tie -> first k
                    bool xok = (unsigned)(x0 + p + 4 * (C - 1)) < (unsigned)IMG_W;
                    if (!(yok && xok)) pk = PKC(fk);
                }
                if (p == 0) pk0 = pk; else pk1 = pk;
            }

            float2 hv = make_float2(__uint_as_float(pk0 & 0xC0000000u),
                                    __uint_as_float(pk1 & 0xC0000000u));
            float2 wv = make_float2(__uint_as_float((pk0 << 2) & 0xC0000000u),
                                    __uint_as_float((pk1 << 2) & 0xC0000000u));
            // 3 bases keep every store offset within STG immediate range
            const int jh = j, jw = j + 9;
            float* ph = (jh < 6) ? b0 + (size_t)jh * PS
                                 : (jh < 12) ? b1 + (size_t)(jh - 6) * PS
                                             : b2 + (size_t)(jh - 12) * PS;
            float* pw = (jw < 12) ? b1 + (size_t)(jw - 6) * PS
                                  : b2 + (size_t)(jw - 12) * PS;
            *(float2*)ph = hv;
            *(float2*)pw = wv;
        }
    }
}

__global__ void __launch_bounds__(BTX * BTY)
DepthOffset_kernel(const float* __restrict__ depth, float* __restrict__ out)
{
    __shared__ __align__(16) float tile[TILE_H][TILE_W];

    const int b   = blockIdx.z;
    const int bx0 = blockIdx.x * TPW;
    const int by0 = blockIdx.y * TPH;
    const int tx  = threadIdx.x, ty = threadIdx.y;
    const int t   = ty * BTX + tx;

    const float* __restrict__ dp = depth + b * PS;

    // whole tile footprint (incl. halo) inside the image?
    const bool safe = (bx0 >= HALO) && (bx0 + TPW + HALO <= IMG_W) &&
                      (by0 >= HALO) && (by0 + TPH + HALO <= IMG_H);

    if (safe) {
        for (int i = t; i < TILE_H * TILE_W; i += BTX * BTY) {
            int r = i / TILE_W;
            int c = i - r * TILE_W;
            tile[r][c] = dp[(by0 - HALO + r) * IMG_W + (bx0 - HALO + c)];
        }
    } else {
        for (int i = t; i < TILE_H * TILE_W; i += BTX * BTY) {
            int r  = i / TILE_W;
            int c  = i - r * TILE_W;
            int gy = by0 - HALO + r;
            int gx = bx0 - HALO + c;
            float v = 0.0f;
            if ((unsigned)gy < (unsigned)IMG_H && (unsigned)gx < (unsigned)IMG_W)
                v = dp[gy * IMG_W + gx];
            tile[r][c] = v;
        }
    }
    __syncthreads();

    const int x0 = bx0 + 2 * tx;
    const int y  = by0 + ty;
    float* __restrict__ base = out + (size_t)(b * 18) * PS + y * IMG_W + x0;
    float* __restrict__ b1   = base + (size_t)6 * PS;
    float* __restrict__ b2   = base + (size_t)12 * PS;

    if (safe)
        compute2<true >(tile, tx, ty, x0, y, base, b1, b2);
    else
        compute2<false>(tile, tx, ty, x0, y, base, b1, b2);
}

extern "C" void kernel_launch(void* const* d_in, const int* in_sizes, int n_in,
                              void* d_out, int out_size)
{
    const float* depth = (const float*)d_in[0];
    float* out = (float*)d_out;

    dim3 block(BTX, BTY);
    dim3 grid(IMG_W / TPW, IMG_H / TPH, NB);   // 10 x 120 x 4 = 4800
    DepthOffset_kernel<<<grid, block>>>(depth, out);
}

// round 14
// speedup vs baseline: 1.0089x; 1.0089x over previous
#include <cuda_runtime.h>
#include <math.h>

#define IMG_H 480
#define IMG_W 640
#define NB    4
#define PS    (IMG_H * IMG_W)

#define BTX   32
#define BTY   8
#define PXT   2                    // pixels per thread along x
#define TPW   (BTX * PXT)          // 64
#define TPH   BTY                  // 8
#define HALO  6
#define TILE_W 80                  // 76 needed, padded to 80
#define TILE_H (TPH + 2 * HALO)    // 20
#define TILES_PER_BLK 3            // 800 blocks x 3 tiles = 2400 tiles, 1 wave

// float bit patterns of -2.0f / 0.0f / +2.0f live entirely in bits [31:30]
#define FB(o)  ((o) == -2 ? 0xC0000000u : ((o) == 2 ? 0x40000000u : 0u))
// pack (off_h, off_w) for candidate k: oh bits in [31:30], ow bits in [29:28]
#define PKC(k) (FB(2*((k)/3 - 1)) | (FB(2*((k)%3 - 1)) >> 2))

__device__ __forceinline__ constexpr unsigned maskRC(int R, int C) {
    // col taps (j=1,7): k in {1,4,7}; row taps (j=3,5): k in {3,4,5}; else all 9
    return ((R != 1) && (C == 1)) ? 0x92u :
           ((R == 1) && (C != 1)) ? 0x38u : 0x1FFu;
}
__device__ __forceinline__ constexpr int firstK(unsigned m) {
    return (m & 1u) ? 0 : ((m & 2u) ? 1 : 3);
}

template<bool SAFE>
__device__ __forceinline__ void compute2(
    const float (&tile)[TILE_H][TILE_W],
    int tx, int ty, int x0, int y,
    float* __restrict__ b0, float* __restrict__ b1, float* __restrict__ b2)
{
    const float cen0 = tile[ty + HALO][2 * tx + HALO];
    const float cen1 = tile[ty + HALO][2 * tx + HALO + 1];

#pragma unroll
    for (int R = 0; R < 3; R++) {
        // group R needs grid rows 2R..2R+2 -> tile rows ty+4R+2r,
        // cols 2tx .. 2tx+13 (14 consecutive floats = 7 LDS.64 per row)
        float s[3][14];
#pragma unroll
        for (int r = 0; r < 3; r++) {
            const float2* src = (const float2*)&tile[ty + 4 * R + 2 * r][2 * tx];
#pragma unroll
            for (int q = 0; q < 7; q++) {
                float2 v = src[q];
                s[r][2 * q]     = v.x;
                s[r][2 * q + 1] = v.y;
            }
        }

        bool yok = true;
        if (!SAFE) yok = (unsigned)(y + 4 * (R - 1)) < (unsigned)IMG_H;

#pragma unroll
        for (int C = 0; C < 3; C++) {
            const int j = 3 * R + C;
            const unsigned mask = maskRC(R, C);
            const int fk = firstK(mask);

            unsigned pk0, pk1;
#pragma unroll
            for (int p = 0; p < PXT; p++) {
                const float cen = (p == 0) ? cen0 : cen1;
                float best = 0.0f;
                unsigned pk = 0u;
                bool first = true;
#pragma unroll
                for (int k = 0; k < 9; k++) {
                    if (!((mask >> k) & 1u)) continue;
                    const int r = k / 3;
                    const int c = k % 3;
                    float v = s[r][p + 4 * C + 2 * c] - cen;
                    if (first) { best = v; pk = PKC(k); first = false; }
                    else {
                        bool pr = fabsf(v) < fabsf(best);  // strict <: first wins
                        best = pr ? v : best;
                        pk   = pr ? PKC(k) : pk;
                    }
                }
                if (!SAFE) {
                    // intermediate index OOB -> all allowed samples tie -> first k
                    bool xok = (unsigned)(x0 + p + 4 * (C - 1)) < (unsigned)IMG_W;
                    if (!(yok && xok)) pk = PKC(fk);
                }
                if (p == 0) pk0 = pk; else pk1 = pk;
            }

            float2 hv = make_float2(__uint_as_float(pk0 & 0xC0000000u),
                                    __uint_as_float(pk1 & 0xC0000000u));
            float2 wv = make_float2(__uint_as_float((pk0 << 2) & 0xC0000000u),
                                    __uint_as_float((pk1 << 2) & 0xC0000000u));
            // 3 bases keep every store offset within STG immediate range
            const int jh = j, jw = j + 9;
            float* ph = (jh < 6) ? b0 + (size_t)jh * PS
                                 : (jh < 12) ? b1 + (size_t)(jh - 6) * PS
                                             : b2 + (size_t)(jh - 12) * PS;
            float* pw = (jw < 12) ? b1 + (size_t)(jw - 6) * PS
                                  : b2 + (size_t)(jw - 12) * PS;
            *(float2*)ph = hv;
            *(float2*)pw = wv;
        }
    }
}

__global__ void __launch_bounds__(BTX * BTY, 6)
DepthOffset_kernel(const float* __restrict__ depth, float* __restrict__ out)
{
    __shared__ __align__(16) float tile[TILE_H][TILE_W];

    const int b   = blockIdx.z;
    const int bx0 = blockIdx.x * TPW;
    const int tx  = threadIdx.x, ty = threadIdx.y;
    const int t   = ty * BTX + tx;

    const float* __restrict__ dp = depth + b * PS;
    const int x0 = bx0 + 2 * tx;

#pragma unroll 1
    for (int kq = 0; kq < TILES_PER_BLK; kq++) {
        const int by0 = (blockIdx.y * TILES_PER_BLK + kq) * TPH;

        if (kq > 0) __syncthreads();   // protect tile reuse

        // whole tile footprint (incl. halo) inside the image?
        const bool safe = (bx0 >= HALO) && (bx0 + TPW + HALO <= IMG_W) &&
                          (by0 >= HALO) && (by0 + TPH + HALO <= IMG_H);

        if (safe) {
            // safe blocks have bx0 <= 512, so even pad cols 76..79 are in range
            for (int i = t; i < TILE_H * TILE_W; i += BTX * BTY) {
                int r = i / TILE_W;
                int c = i - r * TILE_W;
                tile[r][c] = dp[(by0 - HALO + r) * IMG_W + (bx0 - HALO + c)];
            }
        } else {
            for (int i = t; i < TILE_H * TILE_W; i += BTX * BTY) {
                int r  = i / TILE_W;
                int c  = i - r * TILE_W;
                int gy = by0 - HALO + r;
                int gx = bx0 - HALO + c;
                float v = 0.0f;
                if ((unsigned)gy < (unsigned)IMG_H && (unsigned)gx < (unsigned)IMG_W)
                    v = dp[gy * IMG_W + gx];
                tile[r][c] = v;
            }
        }
        __syncthreads();

        const int y = by0 + ty;
        float* __restrict__ base = out + (size_t)(b * 18) * PS + y * IMG_W + x0;
        float* __restrict__ bb1  = base + (size_t)6 * PS;
        float* __restrict__ bb2  = base + (size_t)12 * PS;

        if (safe)
            compute2<true >(tile, tx, ty, x0, y, base, bb1, bb2);
        else
            compute2<false>(tile, tx, ty, x0, y, base, bb1, bb2);
    }
}

extern "C" void kernel_launch(void* const* d_in, const int* in_sizes, int n_in,
                              void* d_out, int out_size)
{
    const float* depth = (const float*)d_in[0];
    float* out = (float*)d_out;

    dim3 block(BTX, BTY);
    dim3 grid(IMG_W / TPW, IMG_H / (TPH * TILES_PER_BLK), NB);  // 10 x 20 x 4 = 800
    DepthOffset_kernel<<<grid, block>>>(depth, out);
}

// round 16
// speedup vs baseline: 1.1125x; 1.1027x over previous
#include <cuda_runtime.h>
#include <math.h>

#define IMG_H 480
#define IMG_W 640
#define NB    4
#define PS    (IMG_H * IMG_W)

#define BTX   32
#define BTY   8
#define PXT   2                    // pixels per thread along x
#define TPW   (BTX * PXT)          // 64
#define TPH   BTY                  // 8
#define HALO  6
#define TILE_W 76
#define TILE_H (TPH + 2 * HALO)    // 20

// float bit patterns of -2.0f / 0.0f / +2.0f live entirely in bits [31:30]
#define FB(o)  ((o) == -2 ? 0xC0000000u : ((o) == 2 ? 0x40000000u : 0u))
// pack (off_h, off_w) for candidate k: oh bits in [31:30], ow bits in [29:28]
#define PKC(k) (FB(2*((k)/3 - 1)) | (FB(2*((k)%3 - 1)) >> 2))

__device__ __forceinline__ constexpr unsigned maskRC(int R, int C) {
    // col taps (j=1,7): k in {1,4,7}; row taps (j=3,5): k in {3,4,5}; else all 9
    return ((R != 1) && (C == 1)) ? 0x92u :
           ((R == 1) && (C != 1)) ? 0x38u : 0x1FFu;
}
__device__ __forceinline__ constexpr int firstK(unsigned m) {
    return (m & 1u) ? 0 : ((m & 2u) ? 1 : 3);
}

template<bool SAFE>
__device__ __forceinline__ void compute2(
    const float (&tile)[TILE_H][TILE_W],
    int tx, int ty, int x0, int y,
    float* __restrict__ b0, float* __restrict__ b1, float* __restrict__ b2)
{
    const float cen0 = tile[ty + HALO][2 * tx + HALO];
    const float cen1 = tile[ty + HALO][2 * tx + HALO + 1];

#pragma unroll
    for (int R = 0; R < 3; R++) {
        // group R needs grid rows 2R..2R+2 -> tile rows ty+4R+2r,
        // cols 2tx .. 2tx+13 (14 consecutive floats = 7 LDS.64 per row)
        float s[3][14];
#pragma unroll
        for (int r = 0; r < 3; r++) {
            const float2* src = (const float2*)&tile[ty + 4 * R + 2 * r][2 * tx];
#pragma unroll
            for (int q = 0; q < 7; q++) {
                float2 v = src[q];
                s[r][2 * q]     = v.x;
                s[r][2 * q + 1] = v.y;
            }
        }

        bool yok = true;
        if (!SAFE) yok = (unsigned)(y + 4 * (R - 1)) < (unsigned)IMG_H;

#pragma unroll
        for (int C = 0; C < 3; C++) {
            const int j = 3 * R + C;
            const unsigned mask = maskRC(R, C);
            const int fk = firstK(mask);

            unsigned pk0, pk1;
#pragma unroll
            for (int p = 0; p < PXT; p++) {
                const float cen = (p == 0) ? cen0 : cen1;
                float best = 0.0f;
                unsigned pk = 0u;
                bool first = true;
#pragma unroll
                for (int k = 0; k < 9; k++) {
                    if (!((mask >> k) & 1u)) continue;
                    const int r = k / 3;
                    const int c = k % 3;
                    float v = s[r][p + 4 * C + 2 * c] - cen;
                    if (first) { best = v; pk = PKC(k); first = false; }
                    else {
                        bool pr = fabsf(v) < fabsf(best);  // strict <: first wins
                        best = pr ? v : best;
                        pk   = pr ? PKC(k) : pk;
                    }
                }
                if (!SAFE) {
                    // intermediate index OOB -> all allowed samples tie -> first k
                    bool xok = (unsigned)(x0 + p + 4 * (C - 1)) < (unsigned)IMG_W;
                    if (!(yok && xok)) pk = PKC(fk);
                }
                if (p == 0) pk0 = pk; else pk1 = pk;
            }

            float2 hv = make_float2(__uint_as_float(pk0 & 0xC0000000u),
                                    __uint_as_float(pk1 & 0xC0000000u));
            float2 wv = make_float2(__uint_as_float((pk0 << 2) & 0xC0000000u),
                                    __uint_as_float((pk1 << 2) & 0xC0000000u));
            // 3 bases keep every store offset within STG immediate range
            const int jh = j, jw = j + 9;
            float* ph = (jh < 6) ? b0 + (size_t)jh * PS
                                 : (jh < 12) ? b1 + (size_t)(jh - 6) * PS
                                             : b2 + (size_t)(jh - 12) * PS;
            float* pw = (jw < 12) ? b1 + (size_t)(jw - 6) * PS
                                  : b2 + (size_t)(jw - 12) * PS;
            *(float2*)ph = hv;
            *(float2*)pw = wv;
        }
    }
}

__global__ void __launch_bounds__(BTX * BTY, 8)   // force regs <= 32: 100% theor. occ
DepthOffset_kernel(const float* __restrict__ depth, float* __restrict__ out)
{
    __shared__ __align__(16) float tile[TILE_H][TILE_W];

    const int b   = blockIdx.z;
    const int bx0 = blockIdx.x * TPW;
    const int by0 = blockIdx.y * TPH;
    const int tx  = threadIdx.x, ty = threadIdx.y;
    const int t   = ty * BTX + tx;

    const float* __restrict__ dp = depth + b * PS;

    // whole tile footprint (incl. halo) inside the image?
    const bool safe = (bx0 >= HALO) && (bx0 + TPW + HALO <= IMG_W) &&
                      (by0 >= HALO) && (by0 + TPH + HALO <= IMG_H);

    if (safe) {
        for (int i = t; i < TILE_H * TILE_W; i += BTX * BTY) {
            int r = i / TILE_W;
            int c = i - r * TILE_W;
            tile[r][c] = dp[(by0 - HALO + r) * IMG_W + (bx0 - HALO + c)];
        }
    } else {
        for (int i = t; i < TILE_H * TILE_W; i += BTX * BTY) {
            int r  = i / TILE_W;
            int c  = i - r * TILE_W;
            int gy = by0 - HALO + r;
            int gx = bx0 - HALO + c;
            float v = 0.0f;
            if ((unsigned)gy < (unsigned)IMG_H && (unsigned)gx < (unsigned)IMG_W)
                v = dp[gy * IMG_W + gx];
            tile[r][c] = v;
        }
    }
    __syncthreads();

    const int x0 = bx0 + 2 * tx;
    const int y  = by0 + ty;
    float* __restrict__ base = out + (size_t)(b * 18) * PS + y * IMG_W + x0;
    float* __restrict__ bb1  = base + (size_t)6 * PS;
    float* __restrict__ bb2  = base + (size_t)12 * PS;

    if (safe)
        compute2<true >(tile, tx, ty, x0, y, base, bb1, bb2);
    else
        compute2<false>(tile, tx, ty, x0, y, base, bb1, bb2);
}

extern "C" void kernel_launch(void* const* d_in, const int* in_sizes, int n_in,
                              void* d_out, int out_size)
{
    const float* depth = (const float*)d_in[0];
    float* out = (float*)d_out;

    dim3 block(BTX, BTY);
    dim3 grid(IMG_W / TPW, IMG_H / TPH, NB);   // 10 x 60 x 4 = 2400
    DepthOffset_kernel<<<grid, block>>>(depth, out);
}